// round 5
// baseline (speedup 1.0000x reference)
#include <cuda_runtime.h>
#include <math.h>

#define BB 16
#define SS 2048
#define DD 512
#define NGROUPS 8
#define GC 64
#define KW 5
#define STILE 256

__device__ float g_actT[BB * DD * SS];   // [b][c][s]; later reused for ln out
__device__ float g_noise[BB * SS * DD];  // [b][s][d]
__device__ float g_inv;

#define FMA_F32X2(d, a, b, c) \
    asm("fma.rn.f32x2 %0, %1, %2, %3;" : "=l"(d) : "l"(a), "l"(b), "l"(c))
#define PACK2(d, lo, hi) \
    asm("mov.b64 %0, {%1, %2};" : "=l"(d) : "r"(lo), "r"(hi))
#define UNPACK2(lo, hi, s) \
    asm("mov.b64 {%0, %1}, %2;" : "=r"(lo), "=r"(hi) : "l"(s))

union PKU { float2 f; unsigned long long u; };
__device__ __forceinline__ float2 caddp(float2 a, float2 b) {
    PKU x, y, r; x.f = a; y.f = b;
    asm("add.rn.f32x2 %0, %1, %2;" : "=l"(r.u) : "l"(x.u), "l"(y.u));
    return r.f;
}
__device__ __forceinline__ float2 csubp(float2 a, float2 b) {
    PKU x, y, r; x.f = a; y.f = b;
    asm("fma.rn.f32x2 %0, %1, %2, %3;"
        : "=l"(r.u) : "l"(y.u), "l"(0xBF800000BF800000ULL), "l"(x.u));
    return r.f;
}
__device__ __forceinline__ float2 cmulc(float2 a, float2 b) {   // a*b
    return make_float2(fmaf(a.x, b.x, -a.y * b.y), fmaf(a.x, b.y, a.y * b.x));
}
__device__ __forceinline__ float2 cmuljc(float2 v, float2 t) {  // v*conj(t)
    return make_float2(fmaf(v.x, t.x, v.y * t.y), fmaf(v.y, t.x, -v.x * t.y));
}
__device__ __forceinline__ float2 C8v(int r) {  // exp(-i*pi*r/8)
    const float c = 0.92387953251128676f, s = 0.38268343236508977f,
                h = 0.70710678118654752f;
    switch (r & 7) {
        case 0: return make_float2(1.f, 0.f);
        case 1: return make_float2(c, -s);
        case 2: return make_float2(h, -h);
        case 3: return make_float2(s, -c);
        case 4: return make_float2(0.f, -1.f);
        case 5: return make_float2(-s, -c);
        case 6: return make_float2(-h, -h);
        default: return make_float2(-c, -s);
    }
}

#define BF(U, V, T)  { float2 _s = caddp(U, V), _d = csubp(U, V); U = _s; V = cmulc(_d, T); }
#define BF1(U, V)    { float2 _s = caddp(U, V), _d = csubp(U, V); U = _s; V = _d; }
#define BI(U, V, T)  { float2 _w = cmuljc(V, T); float2 _u = caddp(U, _w); V = csubp(U, _w); U = _u; }
#define BI1(U, V)    { float2 _w = V; float2 _u = caddp(U, _w); V = csubp(U, _w); U = _u; }

__device__ __forceinline__ void fwd_group4(float2* X, float2 w1) {
    float2 w2 = cmulc(w1, w1), w4 = cmulc(w2, w2), w8 = cmulc(w4, w4);
#pragma unroll
    for (int r = 0; r < 8; ++r) { float2 T = cmulc(w1, C8v(r)); BF(X[r], X[r + 8], T); }
#pragma unroll
    for (int h = 0; h < 16; h += 8)
#pragma unroll
        for (int r = 0; r < 4; ++r) { float2 T = cmulc(w2, C8v(2 * r)); BF(X[h + r], X[h + r + 4], T); }
#pragma unroll
    for (int h = 0; h < 16; h += 4)
#pragma unroll
        for (int r = 0; r < 2; ++r) { float2 T = cmulc(w4, C8v(4 * r)); BF(X[h + r], X[h + r + 2], T); }
#pragma unroll
    for (int h = 0; h < 16; h += 2) BF(X[h], X[h + 1], w8);
}
__device__ __forceinline__ void inv_group4(float2* X, float2 w1) {
    float2 w2 = cmulc(w1, w1), w4 = cmulc(w2, w2), w8 = cmulc(w4, w4);
#pragma unroll
    for (int h = 0; h < 16; h += 2) BI(X[h], X[h + 1], w8);
#pragma unroll
    for (int h = 0; h < 16; h += 4)
#pragma unroll
        for (int r = 0; r < 2; ++r) { float2 T = cmulc(w4, C8v(4 * r)); BI(X[h + r], X[h + r + 2], T); }
#pragma unroll
    for (int h = 0; h < 16; h += 8)
#pragma unroll
        for (int r = 0; r < 4; ++r) { float2 T = cmulc(w2, C8v(2 * r)); BI(X[h + r], X[h + r + 4], T); }
#pragma unroll
    for (int r = 0; r < 8; ++r) { float2 T = cmulc(w1, C8v(r)); BI(X[r], X[r + 8], T); }
}
__device__ __forceinline__ void fwd_group3(float2* X) {
#pragma unroll
    for (int h = 0; h < 16; h += 8) {
#pragma unroll
        for (int r = 0; r < 4; ++r) { float2 T = C8v(2 * r); BF(X[h + r], X[h + r + 4], T); }
#pragma unroll
        for (int u = 0; u < 8; u += 4)
#pragma unroll
            for (int r = 0; r < 2; ++r) { float2 T = C8v(4 * r); BF(X[h + u + r], X[h + u + r + 2], T); }
#pragma unroll
        for (int u = 0; u < 8; u += 2) BF1(X[h + u], X[h + u + 1]);
    }
}
__device__ __forceinline__ void inv_group3(float2* X) {
#pragma unroll
    for (int h = 0; h < 16; h += 8) {
#pragma unroll
        for (int u = 0; u < 8; u += 2) BI1(X[h + u], X[h + u + 1]);
#pragma unroll
        for (int u = 0; u < 8; u += 4)
#pragma unroll
            for (int r = 0; r < 2; ++r) { float2 T = C8v(4 * r); BI(X[h + u + r], X[h + u + r + 2], T); }
#pragma unroll
        for (int r = 0; r < 4; ++r) { float2 T = C8v(2 * r); BI(X[h + r], X[h + r + 4], T); }
    }
}

#define SF(a) ((a) + ((a) >> 4))

// ---------------------------------------------------------------- kernel 0
__global__ void k0_norm(const float* __restrict__ ff) {
    __shared__ float red[256];
    int tid = threadIdx.x;
    float v = 0.f;
    for (int i = tid; i < DD; i += 256) { float f = ff[i]; v += f * f; }
    red[tid] = v;
    __syncthreads();
    for (int s = 128; s > 0; s >>= 1) {
        if (tid < s) red[tid] += red[tid + s];
        __syncthreads();
    }
    if (tid == 0) g_inv = 1.0f / fmaxf(sqrtf(red[0]), 1e-12f);
}

// ---------------------------------------------------------------- kernel 1
__global__ void __launch_bounds__(512) k1_conv(
    const float* __restrict__ x, const float* __restrict__ ff,
    const float* __restrict__ w, const float* __restrict__ cb)
{
    extern __shared__ float sm[];
    float* ysm = sm;                   // [64][264]
    float* wsm = sm + GC * 264;        // [i][k][o]

    const int g  = blockIdx.y;
    const int b  = blockIdx.z;
    const int s0 = blockIdx.x * STILE;
    const int tid = threadIdx.x;
    const float inv = g_inv;

    for (int idx = tid; idx < GC * GC * KW; idx += 512) {
        int o = idx / (GC * KW);
        int r = idx - o * (GC * KW);
        int i = r / KW;
        int k = r - i * KW;
        wsm[(i * KW + k) * GC + o] = w[((g * GC + o) * GC + i) * KW + k];
    }
    for (int idx = tid; idx < 260 * GC; idx += 512) {
        int i  = idx & 63;
        int j  = idx >> 6;
        int sg = s0 + j - 2;
        float v = 0.f;
        if (sg >= 0 && sg < SS) {
            int c = g * GC + i;
            v = x[(b * SS + sg) * DD + c] * (ff[c] * inv);
            v = fminf(fmaxf(v, -10.f), 10.f);
        }
        ysm[i * 264 + j] = v;
    }
    __syncthreads();

    const int so = tid & 63;
    const int oo = tid >> 6;

    unsigned long long acc2[4][4];
#pragma unroll
    for (int a = 0; a < 4; ++a)
#pragma unroll
        for (int c = 0; c < 4; ++c) acc2[a][c] = 0ull;

#pragma unroll 2
    for (int i = 0; i < GC; ++i) {
        const float* yr = &ysm[i * 264 + so * 4];
        float4 y0 = *(const float4*)(yr);
        float4 y1 = *(const float4*)(yr + 4);
        float ya[8] = {y0.x, y0.y, y0.z, y0.w, y1.x, y1.y, y1.z, y1.w};
        unsigned long long y2[8];
#pragma unroll
        for (int j = 0; j < 8; ++j) {
            unsigned int u = __float_as_uint(ya[j]);
            PACK2(y2[j], u, u);
        }
#pragma unroll
        for (int k = 0; k < KW; ++k) {
            const float* wr = &wsm[(i * KW + k) * GC + oo * 8];
            ulonglong2 wa = *(const ulonglong2*)(wr);
            ulonglong2 wb = *(const ulonglong2*)(wr + 4);
            unsigned long long w2[4] = {wa.x, wa.y, wb.x, wb.y};
#pragma unroll
            for (int ts = 0; ts < 4; ++ts)
#pragma unroll
                for (int op = 0; op < 4; ++op)
                    FMA_F32X2(acc2[ts][op], y2[ts + k], w2[op], acc2[ts][op]);
        }
    }

#pragma unroll
    for (int op = 0; op < 4; ++op) {
#pragma unroll
        for (int h = 0; h < 2; ++h) {
            int ol = oo * 8 + op * 2 + h;
            float bias = cb[g * GC + ol];
            float4 o4;
            float* po = (float*)&o4;
#pragma unroll
            for (int ts = 0; ts < 4; ++ts) {
                unsigned int lo, hi;
                UNPACK2(lo, hi, acc2[ts][op]);
                float av = __uint_as_float(h ? hi : lo);
                float filt = ysm[ol * 264 + so * 4 + ts + 2];
                po[ts] = tanhf(av + bias) + 0.1f * filt;
            }
            *(float4*)&g_actT[((b * DD) + g * GC + ol) * SS + s0 + so * 4] = o4;
        }
    }
}

// ---------------------------------------------------------------- kernel 2
// Register-resident FFT: 2 complex seqs (4 channels) of 2048 per block,
// 256 threads, 16 points/thread. Reg budget 85 (launch_bounds 256,3) so
// nothing spills; 24 warps/SM.
__global__ void __launch_bounds__(256, 3) k2_fft()
{
    extern __shared__ float2 Zs[];      // 2 * 2176
    const int tid = threadIdx.x;
    const int q = tid >> 7;             // seq 0..1
    const int t = tid & 127;
    const int b  = blockIdx.y;
    const int d0 = blockIdx.x * 4;
    float2* Sq = Zs + q * 2176;

    // load: layout A, a = t + 128r
    float2 X[16];
    const float* pa = &g_actT[((b * DD) + d0 + 2 * q) * SS];
    const float* pb = pa + SS;
#pragma unroll
    for (int r = 0; r < 16; ++r) {
        int n = t + 128 * r;
        X[r] = make_float2(pa[n], pb[n]);
    }

    float sv, cv;
    sincosf(-3.14159265358979323846f * (float)t * (1.0f / 1024.0f), &sv, &cv);
    float2 wA = make_float2(cv, sv);

    fwd_group4(X, wA);                  // spans 1024,512,256,128

    // exchange A -> B  (B: a = hi*128 + 8m + lo)
#pragma unroll
    for (int r = 0; r < 16; ++r) Sq[SF(t + 128 * r)] = X[r];
    __syncthreads();
    const int hi = t >> 3, lo = t & 7;
#pragma unroll
    for (int m = 0; m < 16; ++m) X[m] = Sq[SF(hi * 128 + 8 * m + lo)];

    sincosf(-3.14159265358979323846f * (float)lo * (1.0f / 64.0f), &sv, &cv);
    float2 wB = make_float2(cv, sv);

    fwd_group4(X, wB);                  // spans 64,32,16,8

    // exchange B -> C  (C: a = hi*128 + lo*16 + e)
    __syncthreads();
#pragma unroll
    for (int m = 0; m < 16; ++m) Sq[SF(hi * 128 + 8 * m + lo)] = X[m];
    __syncthreads();
    const int abase = hi * 128 + lo * 16;
#pragma unroll
    for (int e = 0; e < 16; ++e) X[e] = Sq[SF(abase + e)];

    fwd_group3(X);                      // spans 4,2,1

    // spectral scaling at bit-reversed indices (+1/N)
#pragma unroll
    for (int e = 0; e < 16; ++e) {
        int a = abase + e;
        int k = __brev((unsigned)a) >> 21;
        int kk = min(k, 2048 - k);
        float base = sqrtf((float)kk * (1.0f / 2048.0f) + 1e-8f);
        base = fminf(fmaxf(base, 1e-8f), 1e6f);
        float sc = (1.0f / base) * (1.0f / 2048.0f);
        X[e].x *= sc;
        X[e].y *= sc;
    }

    inv_group3(X);                      // spans 1,2,4

    // exchange C -> B
    __syncthreads();
#pragma unroll
    for (int e = 0; e < 16; ++e) Sq[SF(abase + e)] = X[e];
    __syncthreads();
#pragma unroll
    for (int m = 0; m < 16; ++m) X[m] = Sq[SF(hi * 128 + 8 * m + lo)];

    inv_group4(X, wB);                  // spans 8,16,32,64

    // exchange B -> A
    __syncthreads();
#pragma unroll
    for (int m = 0; m < 16; ++m) Sq[SF(hi * 128 + 8 * m + lo)] = X[m];
    __syncthreads();
#pragma unroll
    for (int r = 0; r < 16; ++r) X[r] = Sq[SF(t + 128 * r)];

    inv_group4(X, wA);                  // spans 128,256,512,1024

    // clip + stage + store (16B per row)
    __syncthreads();
#pragma unroll
    for (int r = 0; r < 16; ++r) {
        float2 c = X[r];
        c.x = fminf(fmaxf(c.x, -10.f), 10.f);
        c.y = fminf(fmaxf(c.y, -10.f), 10.f);
        Sq[SF(t + 128 * r)] = c;
    }
    __syncthreads();
#pragma unroll 1
    for (int it = 0; it < 8; ++it) {
        int n = tid + it * 256;
        float2 z0 = Zs[0 * 2176 + SF(n)];
        float2 z1 = Zs[1 * 2176 + SF(n)];
        float* dst = &g_noise[(b * SS + n) * DD + d0];
        *(float4*)dst = make_float4(z0.x, z0.y, z1.x, z1.y);
    }
}

// ---------------------------------------------------------------- kernel 3
__global__ void __launch_bounds__(512) k3_ln(const float* __restrict__ gamma,
                                             const float* __restrict__ beta)
{
    int warp = threadIdx.x >> 5, lane = threadIdx.x & 31;
    int row = blockIdx.x * 16 + warp;
    const float* src = g_noise + row * DD;
    float4 v4[4];
    float sum = 0.f;
#pragma unroll
    for (int j = 0; j < 4; ++j) {
        v4[j] = *(const float4*)&src[(lane + j * 32) * 4];
        sum += v4[j].x + v4[j].y + v4[j].z + v4[j].w;
    }
#pragma unroll
    for (int o = 16; o; o >>= 1) sum += __shfl_xor_sync(0xffffffffu, sum, o);
    float mu = sum * (1.0f / 512.0f);
    float sq = 0.f;
#pragma unroll
    for (int j = 0; j < 4; ++j) {
        float a0 = v4[j].x - mu, a1 = v4[j].y - mu, a2 = v4[j].z - mu, a3 = v4[j].w - mu;
        sq += a0 * a0 + a1 * a1 + a2 * a2 + a3 * a3;
    }
#pragma unroll
    for (int o = 16; o; o >>= 1) sq += __shfl_xor_sync(0xffffffffu, sq, o);
    float rstd = rsqrtf(sq * (1.0f / 512.0f) + 1e-5f);
    float* dst = g_actT + row * DD;
#pragma unroll
    for (int j = 0; j < 4; ++j) {
        int d = (lane + j * 32) * 4;
        float4 gm = *(const float4*)&gamma[d];
        float4 bt = *(const float4*)&beta[d];
        float4 o4;
        o4.x = (v4[j].x - mu) * rstd * gm.x + bt.x;
        o4.y = (v4[j].y - mu) * rstd * gm.y + bt.y;
        o4.z = (v4[j].z - mu) * rstd * gm.z + bt.z;
        o4.w = (v4[j].w - mu) * rstd * gm.w + bt.w;
        *(float4*)&dst[d] = o4;
    }
}

// ---------------------------------------------------------------- kernel 4
// EMA over t; chunks of 512 outputs with 256-step lookback ((15/16)^256~7e-8).
__global__ void __launch_bounds__(128) k4_ema(float* __restrict__ out)
{
    const int d  = blockIdx.z * 128 + threadIdx.x;
    const int b  = blockIdx.y;
    const int t0 = blockIdx.x * 512;
    const float* src = g_actT + (b * SS) * DD + d;
    float* dst = out + (b * SS) * DD + d;
    const float a = 0.0625f, na = 0.9375f;
    float m;
    int t;
    if (t0 == 0) {
        m = src[0];
        dst[0] = m;
        t = 1;
    } else {
        m = 0.f;
        t = t0 - 256;
    }
    const int tend = t0 + 512;
    for (; t < t0; ++t) m = fmaf(na, m, a * src[t * DD]);
    for (; t < tend; ++t) {
        m = fmaf(na, m, a * src[t * DD]);
        dst[t * DD] = m;
    }
}

// ---------------------------------------------------------------- launch
extern "C" void kernel_launch(void* const* d_in, const int* in_sizes, int n_in,
                              void* d_out, int out_size)
{
    const float* x     = (const float*)d_in[0];
    const float* ff    = (const float*)d_in[1];
    const float* cw    = (const float*)d_in[2];
    const float* cb    = (const float*)d_in[3];
    const float* gamma = (const float*)d_in[4];
    const float* beta  = (const float*)d_in[5];
    float* out = (float*)d_out;

    const int k1_smem = (GC * 264 + GC * KW * GC) * (int)sizeof(float);
    const int k2_smem = 2 * 2176 * (int)sizeof(float2);
    cudaFuncSetAttribute(k1_conv, cudaFuncAttributeMaxDynamicSharedMemorySize, k1_smem);
    cudaFuncSetAttribute(k2_fft,  cudaFuncAttributeMaxDynamicSharedMemorySize, k2_smem);

    k0_norm<<<1, 256>>>(ff);
    k1_conv<<<dim3(SS / STILE, NGROUPS, BB), 512, k1_smem>>>(x, ff, cw, cb);
    k2_fft<<<dim3(DD / 4, BB), 256, k2_smem>>>();
    k3_ln<<<(BB * SS) / 16, 512>>>(gamma, beta);
    k4_ema<<<dim3(SS / 512, BB, 4), 128>>>(out);
}

// round 6
// speedup vs baseline: 1.0308x; 1.0308x over previous
#include <cuda_runtime.h>
#include <math.h>

#define BB 16
#define SS 2048
#define DD 512
#define NGROUPS 8
#define GC 64
#define KW 5
#define STILE 256

__device__ float g_actT[BB * DD * SS];   // [b][c][s]; later reused for ln out
__device__ float g_noise[BB * SS * DD];  // [b][s][d]
__device__ float g_inv;

#define FMA_F32X2(d, a, b, c) \
    asm("fma.rn.f32x2 %0, %1, %2, %3;" : "=l"(d) : "l"(a), "l"(b), "l"(c))
#define PACK2(d, lo, hi) \
    asm("mov.b64 %0, {%1, %2};" : "=l"(d) : "r"(lo), "r"(hi))
#define UNPACK2(lo, hi, s) \
    asm("mov.b64 {%0, %1}, %2;" : "=r"(lo), "=r"(hi) : "l"(s))

union PKU { float2 f; unsigned long long u; };
__device__ __forceinline__ float2 caddp(float2 a, float2 b) {
    PKU x, y, r; x.f = a; y.f = b;
    asm("add.rn.f32x2 %0, %1, %2;" : "=l"(r.u) : "l"(x.u), "l"(y.u));
    return r.f;
}
__device__ __forceinline__ float2 csubp(float2 a, float2 b) {
    PKU x, y, r; x.f = a; y.f = b;
    asm("fma.rn.f32x2 %0, %1, %2, %3;"
        : "=l"(r.u) : "l"(y.u), "l"(0xBF800000BF800000ULL), "l"(x.u));
    return r.f;
}
__device__ __forceinline__ float2 cmulc(float2 a, float2 b) {   // a*b
    return make_float2(fmaf(a.x, b.x, -a.y * b.y), fmaf(a.x, b.y, a.y * b.x));
}
__device__ __forceinline__ float2 cmuljc(float2 v, float2 t) {  // v*conj(t)
    return make_float2(fmaf(v.x, t.x, v.y * t.y), fmaf(v.y, t.x, -v.x * t.y));
}
__device__ __forceinline__ float2 C8v(int r) {  // exp(-i*pi*r/8)
    const float c = 0.92387953251128676f, s = 0.38268343236508977f,
                h = 0.70710678118654752f;
    switch (r & 7) {
        case 0: return make_float2(1.f, 0.f);
        case 1: return make_float2(c, -s);
        case 2: return make_float2(h, -h);
        case 3: return make_float2(s, -c);
        case 4: return make_float2(0.f, -1.f);
        case 5: return make_float2(-s, -c);
        case 6: return make_float2(-h, -h);
        default: return make_float2(-c, -s);
    }
}

#define BF(U, V, T)  { float2 _s = caddp(U, V), _d = csubp(U, V); U = _s; V = cmulc(_d, T); }
#define BF1(U, V)    { float2 _s = caddp(U, V), _d = csubp(U, V); U = _s; V = _d; }
#define BI(U, V, T)  { float2 _w = cmuljc(V, T); float2 _u = caddp(U, _w); V = csubp(U, _w); U = _u; }
#define BI1(U, V)    { float2 _w = V; float2 _u = caddp(U, _w); V = csubp(U, _w); U = _u; }

__device__ __forceinline__ void fwd_group4(float2* X, float2 w1) {
    float2 w2 = cmulc(w1, w1), w4 = cmulc(w2, w2), w8 = cmulc(w4, w4);
#pragma unroll
    for (int r = 0; r < 8; ++r) { float2 T = cmulc(w1, C8v(r)); BF(X[r], X[r + 8], T); }
#pragma unroll
    for (int h = 0; h < 16; h += 8)
#pragma unroll
        for (int r = 0; r < 4; ++r) { float2 T = cmulc(w2, C8v(2 * r)); BF(X[h + r], X[h + r + 4], T); }
#pragma unroll
    for (int h = 0; h < 16; h += 4)
#pragma unroll
        for (int r = 0; r < 2; ++r) { float2 T = cmulc(w4, C8v(4 * r)); BF(X[h + r], X[h + r + 2], T); }
#pragma unroll
    for (int h = 0; h < 16; h += 2) BF(X[h], X[h + 1], w8);
}
__device__ __forceinline__ void inv_group4(float2* X, float2 w1) {
    float2 w2 = cmulc(w1, w1), w4 = cmulc(w2, w2), w8 = cmulc(w4, w4);
#pragma unroll
    for (int h = 0; h < 16; h += 2) BI(X[h], X[h + 1], w8);
#pragma unroll
    for (int h = 0; h < 16; h += 4)
#pragma unroll
        for (int r = 0; r < 2; ++r) { float2 T = cmulc(w4, C8v(4 * r)); BI(X[h + r], X[h + r + 2], T); }
#pragma unroll
    for (int h = 0; h < 16; h += 8)
#pragma unroll
        for (int r = 0; r < 4; ++r) { float2 T = cmulc(w2, C8v(2 * r)); BI(X[h + r], X[h + r + 4], T); }
#pragma unroll
    for (int r = 0; r < 8; ++r) { float2 T = cmulc(w1, C8v(r)); BI(X[r], X[r + 8], T); }
}
__device__ __forceinline__ void fwd_group3(float2* X) {
#pragma unroll
    for (int h = 0; h < 16; h += 8) {
#pragma unroll
        for (int r = 0; r < 4; ++r) { float2 T = C8v(2 * r); BF(X[h + r], X[h + r + 4], T); }
#pragma unroll
        for (int u = 0; u < 8; u += 4)
#pragma unroll
            for (int r = 0; r < 2; ++r) { float2 T = C8v(4 * r); BF(X[h + u + r], X[h + u + r + 2], T); }
#pragma unroll
        for (int u = 0; u < 8; u += 2) BF1(X[h + u], X[h + u + 1]);
    }
}
__device__ __forceinline__ void inv_group3(float2* X) {
#pragma unroll
    for (int h = 0; h < 16; h += 8) {
#pragma unroll
        for (int u = 0; u < 8; u += 2) BI1(X[h + u], X[h + u + 1]);
#pragma unroll
        for (int u = 0; u < 8; u += 4)
#pragma unroll
            for (int r = 0; r < 2; ++r) { float2 T = C8v(4 * r); BI(X[h + u + r], X[h + u + r + 2], T); }
#pragma unroll
        for (int r = 0; r < 4; ++r) { float2 T = C8v(2 * r); BI(X[h + r], X[h + r + 4], T); }
    }
}

#define SF(a) ((a) + ((a) >> 4))

// ---------------------------------------------------------------- kernel 0
__global__ void k0_norm(const float* __restrict__ ff) {
    __shared__ float red[256];
    int tid = threadIdx.x;
    float v = 0.f;
    for (int i = tid; i < DD; i += 256) { float f = ff[i]; v += f * f; }
    red[tid] = v;
    __syncthreads();
    for (int s = 128; s > 0; s >>= 1) {
        if (tid < s) red[tid] += red[tid + s];
        __syncthreads();
    }
    if (tid == 0) g_inv = 1.0f / fmaxf(sqrtf(red[0]), 1e-12f);
}

// probe: no-op launch to shift the ncu skip-window onto k2_fft
__global__ void kp_probe() {}

// ---------------------------------------------------------------- kernel 1
__global__ void __launch_bounds__(512) k1_conv(
    const float* __restrict__ x, const float* __restrict__ ff,
    const float* __restrict__ w, const float* __restrict__ cb)
{
    extern __shared__ float sm[];
    float* ysm = sm;                   // [64][264]
    float* wsm = sm + GC * 264;        // [i][k][o]

    const int g  = blockIdx.y;
    const int b  = blockIdx.z;
    const int s0 = blockIdx.x * STILE;
    const int tid = threadIdx.x;
    const float inv = g_inv;

    for (int idx = tid; idx < GC * GC * KW; idx += 512) {
        int o = idx / (GC * KW);
        int r = idx - o * (GC * KW);
        int i = r / KW;
        int k = r - i * KW;
        wsm[(i * KW + k) * GC + o] = w[((g * GC + o) * GC + i) * KW + k];
    }
    for (int idx = tid; idx < 260 * GC; idx += 512) {
        int i  = idx & 63;
        int j  = idx >> 6;
        int sg = s0 + j - 2;
        float v = 0.f;
        if (sg >= 0 && sg < SS) {
            int c = g * GC + i;
            v = x[(b * SS + sg) * DD + c] * (ff[c] * inv);
            v = fminf(fmaxf(v, -10.f), 10.f);
        }
        ysm[i * 264 + j] = v;
    }
    __syncthreads();

    const int so = tid & 63;
    const int oo = tid >> 6;

    unsigned long long acc2[4][4];
#pragma unroll
    for (int a = 0; a < 4; ++a)
#pragma unroll
        for (int c = 0; c < 4; ++c) acc2[a][c] = 0ull;

#pragma unroll 2
    for (int i = 0; i < GC; ++i) {
        const float* yr = &ysm[i * 264 + so * 4];
        float4 y0 = *(const float4*)(yr);
        float4 y1 = *(const float4*)(yr + 4);
        float ya[8] = {y0.x, y0.y, y0.z, y0.w, y1.x, y1.y, y1.z, y1.w};
        unsigned long long y2[8];
#pragma unroll
        for (int j = 0; j < 8; ++j) {
            unsigned int u = __float_as_uint(ya[j]);
            PACK2(y2[j], u, u);
        }
#pragma unroll
        for (int k = 0; k < KW; ++k) {
            const float* wr = &wsm[(i * KW + k) * GC + oo * 8];
            ulonglong2 wa = *(const ulonglong2*)(wr);
            ulonglong2 wb = *(const ulonglong2*)(wr + 4);
            unsigned long long w2[4] = {wa.x, wa.y, wb.x, wb.y};
#pragma unroll
            for (int ts = 0; ts < 4; ++ts)
#pragma unroll
                for (int op = 0; op < 4; ++op)
                    FMA_F32X2(acc2[ts][op], y2[ts + k], w2[op], acc2[ts][op]);
        }
    }

#pragma unroll
    for (int op = 0; op < 4; ++op) {
#pragma unroll
        for (int h = 0; h < 2; ++h) {
            int ol = oo * 8 + op * 2 + h;
            float bias = cb[g * GC + ol];
            float4 o4;
            float* po = (float*)&o4;
#pragma unroll
            for (int ts = 0; ts < 4; ++ts) {
                unsigned int lo, hi;
                UNPACK2(lo, hi, acc2[ts][op]);
                float av = __uint_as_float(h ? hi : lo) + bias;
                // fast tanh: 1 - 2/(e^{2x}+1); saturates correctly at +-inf
                float e2 = __expf(2.0f * av);
                float th = 1.0f - __fdividef(2.0f, e2 + 1.0f);
                float filt = ysm[ol * 264 + so * 4 + ts + 2];
                po[ts] = th + 0.1f * filt;
            }
            *(float4*)&g_actT[((b * DD) + g * GC + ol) * SS + s0 + so * 4] = o4;
        }
    }
}

// ---------------------------------------------------------------- kernel 2
// Register-resident FFT: 2 complex seqs (4 channels) of 2048 per block,
// 256 threads, 16 points/thread.
__global__ void __launch_bounds__(256, 3) k2_fft()
{
    extern __shared__ float2 Zs[];      // 2 * 2176
    const int tid = threadIdx.x;
    const int q = tid >> 7;             // seq 0..1
    const int t = tid & 127;
    const int b  = blockIdx.y;
    const int d0 = blockIdx.x * 4;
    float2* Sq = Zs + q * 2176;

    // load: layout A, a = t + 128r
    float2 X[16];
    const float* pa = &g_actT[((b * DD) + d0 + 2 * q) * SS];
    const float* pb = pa + SS;
#pragma unroll
    for (int r = 0; r < 16; ++r) {
        int n = t + 128 * r;
        X[r] = make_float2(pa[n], pb[n]);
    }

    float sv, cv;
    __sincosf(-3.14159265358979323846f * (float)t * (1.0f / 1024.0f), &sv, &cv);
    float2 wA = make_float2(cv, sv);

    fwd_group4(X, wA);                  // spans 1024,512,256,128

    // exchange A -> B  (B: a = hi*128 + 8m + lo)
#pragma unroll
    for (int r = 0; r < 16; ++r) Sq[SF(t + 128 * r)] = X[r];
    __syncthreads();
    const int hi = t >> 3, lo = t & 7;
#pragma unroll
    for (int m = 0; m < 16; ++m) X[m] = Sq[SF(hi * 128 + 8 * m + lo)];

    __sincosf(-3.14159265358979323846f * (float)lo * (1.0f / 64.0f), &sv, &cv);
    float2 wB = make_float2(cv, sv);

    fwd_group4(X, wB);                  // spans 64,32,16,8

    // exchange B -> C  (C: a = hi*128 + lo*16 + e)
    __syncthreads();
#pragma unroll
    for (int m = 0; m < 16; ++m) Sq[SF(hi * 128 + 8 * m + lo)] = X[m];
    __syncthreads();
    const int abase = hi * 128 + lo * 16;
#pragma unroll
    for (int e = 0; e < 16; ++e) X[e] = Sq[SF(abase + e)];

    fwd_group3(X);                      // spans 4,2,1

    // spectral scaling at bit-reversed indices (+1/N).
    // base = sqrt(kk/2048 + 1e-8) in [1e-4, 0.71] so the reference clamps
    // [1e-8, 1e6] are dead; sc = rsqrt(arg)/2048 exactly.
#pragma unroll
    for (int e = 0; e < 16; ++e) {
        int a = abase + e;
        int k = __brev((unsigned)a) >> 21;
        int kk = min(k, 2048 - k);
        float sc = rsqrtf((float)kk * (1.0f / 2048.0f) + 1e-8f) * (1.0f / 2048.0f);
        X[e].x *= sc;
        X[e].y *= sc;
    }

    inv_group3(X);                      // spans 1,2,4

    // exchange C -> B
    __syncthreads();
#pragma unroll
    for (int e = 0; e < 16; ++e) Sq[SF(abase + e)] = X[e];
    __syncthreads();
#pragma unroll
    for (int m = 0; m < 16; ++m) X[m] = Sq[SF(hi * 128 + 8 * m + lo)];

    inv_group4(X, wB);                  // spans 8,16,32,64

    // exchange B -> A
    __syncthreads();
#pragma unroll
    for (int m = 0; m < 16; ++m) Sq[SF(hi * 128 + 8 * m + lo)] = X[m];
    __syncthreads();
#pragma unroll
    for (int r = 0; r < 16; ++r) X[r] = Sq[SF(t + 128 * r)];

    inv_group4(X, wA);                  // spans 128,256,512,1024

    // clip + stage + store (16B per row)
    __syncthreads();
#pragma unroll
    for (int r = 0; r < 16; ++r) {
        float2 c = X[r];
        c.x = fminf(fmaxf(c.x, -10.f), 10.f);
        c.y = fminf(fmaxf(c.y, -10.f), 10.f);
        Sq[SF(t + 128 * r)] = c;
    }
    __syncthreads();
#pragma unroll 1
    for (int it = 0; it < 8; ++it) {
        int n = tid + it * 256;
        float2 z0 = Zs[0 * 2176 + SF(n)];
        float2 z1 = Zs[1 * 2176 + SF(n)];
        float* dst = &g_noise[(b * SS + n) * DD + d0];
        *(float4*)dst = make_float4(z0.x, z0.y, z1.x, z1.y);
    }
}

// ---------------------------------------------------------------- kernel 3
__global__ void __launch_bounds__(512) k3_ln(const float* __restrict__ gamma,
                                             const float* __restrict__ beta)
{
    int warp = threadIdx.x >> 5, lane = threadIdx.x & 31;
    int row = blockIdx.x * 16 + warp;
    const float* src = g_noise + row * DD;
    float4 v4[4];
    float sum = 0.f;
#pragma unroll
    for (int j = 0; j < 4; ++j) {
        v4[j] = *(const float4*)&src[(lane + j * 32) * 4];
        sum += v4[j].x + v4[j].y + v4[j].z + v4[j].w;
    }
#pragma unroll
    for (int o = 16; o; o >>= 1) sum += __shfl_xor_sync(0xffffffffu, sum, o);
    float mu = sum * (1.0f / 512.0f);
    float sq = 0.f;
#pragma unroll
    for (int j = 0; j < 4; ++j) {
        float a0 = v4[j].x - mu, a1 = v4[j].y - mu, a2 = v4[j].z - mu, a3 = v4[j].w - mu;
        sq += a0 * a0 + a1 * a1 + a2 * a2 + a3 * a3;
    }
#pragma unroll
    for (int o = 16; o; o >>= 1) sq += __shfl_xor_sync(0xffffffffu, sq, o);
    float rstd = rsqrtf(sq * (1.0f / 512.0f) + 1e-5f);
    float* dst = g_actT + row * DD;
#pragma unroll
    for (int j = 0; j < 4; ++j) {
        int d = (lane + j * 32) * 4;
        float4 gm = *(const float4*)&gamma[d];
        float4 bt = *(const float4*)&beta[d];
        float4 o4;
        o4.x = (v4[j].x - mu) * rstd * gm.x + bt.x;
        o4.y = (v4[j].y - mu) * rstd * gm.y + bt.y;
        o4.z = (v4[j].z - mu) * rstd * gm.z + bt.z;
        o4.w = (v4[j].w - mu) * rstd * gm.w + bt.w;
        *(float4*)&dst[d] = o4;
    }
}

// ---------------------------------------------------------------- kernel 4
__global__ void __launch_bounds__(128) k4_ema(float* __restrict__ out)
{
    const int d  = blockIdx.z * 128 + threadIdx.x;
    const int b  = blockIdx.y;
    const int t0 = blockIdx.x * 512;
    const float* src = g_actT + (b * SS) * DD + d;
    float* dst = out + (b * SS) * DD + d;
    const float a = 0.0625f, na = 0.9375f;
    float m;
    int t;
    if (t0 == 0) {
        m = src[0];
        dst[0] = m;
        t = 1;
    } else {
        m = 0.f;
        t = t0 - 256;
    }
    const int tend = t0 + 512;
    for (; t < t0; ++t) m = fmaf(na, m, a * src[t * DD]);
    for (; t < tend; ++t) {
        m = fmaf(na, m, a * src[t * DD]);
        dst[t * DD] = m;
    }
}

// ---------------------------------------------------------------- launch
extern "C" void kernel_launch(void* const* d_in, const int* in_sizes, int n_in,
                              void* d_out, int out_size)
{
    const float* x     = (const float*)d_in[0];
    const float* ff    = (const float*)d_in[1];
    const float* cw    = (const float*)d_in[2];
    const float* cb    = (const float*)d_in[3];
    const float* gamma = (const float*)d_in[4];
    const float* beta  = (const float*)d_in[5];
    float* out = (float*)d_out;

    const int k1_smem = (GC * 264 + GC * KW * GC) * (int)sizeof(float);
    const int k2_smem = 2 * 2176 * (int)sizeof(float2);
    cudaFuncSetAttribute(k1_conv, cudaFuncAttributeMaxDynamicSharedMemorySize, k1_smem);
    cudaFuncSetAttribute(k2_fft,  cudaFuncAttributeMaxDynamicSharedMemorySize, k2_smem);

    k0_norm<<<1, 256>>>(ff);
    kp_probe<<<1, 32>>>();   // shifts ncu's skip-window onto k2_fft
    k1_conv<<<dim3(SS / STILE, NGROUPS, BB), 512, k1_smem>>>(x, ff, cw, cb);
    k2_fft<<<dim3(DD / 4, BB), 256, k2_smem>>>();
    k3_ln<<<(BB * SS) / 16, 512>>>(gamma, beta);
    k4_ema<<<dim3(SS / 512, BB, 4), 128>>>(out);
}